// round 2
// baseline (speedup 1.0000x reference)
#include <cuda_runtime.h>
#include <math.h>
#include <stdint.h>

#define NN    50000
#define DD    128
#define EADJ  800000
#define EPRED 500000
#define BNEPS 1e-5f

// ---------------- scratch ----------------------------------------------------
__device__ float g_support[NN * DD];
__device__ float g_tmp[NN * DD];
__device__ float g_h1[NN * DD];
__device__ float g_h2[NN * DD];
__device__ float g_stats[2 * DD];
__device__ float g_s1[NN];
__device__ float g_s2[NN];

// ---------------- helpers ----------------------------------------------------
__device__ __forceinline__ float f2tf32(float f) {
    uint32_t r;
    asm("cvt.rna.tf32.f32 %0, %1;" : "=r"(r) : "f"(f));
    return __uint_as_float(r);
}

__device__ __forceinline__ void mma_tf32(float* c, const uint32_t* a, const uint32_t* b) {
    asm volatile(
        "mma.sync.aligned.m16n8k8.row.col.f32.tf32.tf32.f32 "
        "{%0,%1,%2,%3}, {%4,%5,%6,%7}, {%8,%9}, {%0,%1,%2,%3};\n"
        : "+f"(c[0]), "+f"(c[1]), "+f"(c[2]), "+f"(c[3])
        : "r"(a[0]), "r"(a[1]), "r"(a[2]), "r"(a[3]), "r"(b[0]), "r"(b[1]));
}

// ---------------- tf32 tensor-core dual GEMM --------------------------------
// grid.x = M tiles of 128; grid.y: 0 -> support = A@W, 1 -> tmp = A@Wself + b
// Block: 256 threads = 8 warps (4 row groups x 2 col groups), warp tile 32x64.
// smem strides chosen so fragment LDS.64 are bank-conflict-free:
//   element index stride per groupID g is 20 float2 = 40 words, 40%32=8, so
//   half-warp banks = 8*g + 2*tig (+1): all 32 distinct.
__global__ __launch_bounds__(256, 2) void gemm_tc(
    const float* __restrict__ A,
    const float* __restrict__ W,
    const float* __restrict__ Wself,
    const float* __restrict__ bias,
    float* __restrict__ support,
    float* __restrict__ outtmp)
{
    // A chunk: 128 rows x 16 k. Packed: As[rp][k] = (row mt*16+p, row mt*16+8+p)
    // where rp = mt*8 + p.  64 row-pairs, k stride 20.
    __shared__ float2 As[64 * 20];
    // B chunk: 16 k x 128 n. Packed: Bs[n][kp] = (k = ks*8+tig, k = ks*8+tig+4)
    // where kp = ks*4 + tig (0..7), stride 20.
    __shared__ float2 Bs[128 * 20];

    const int   by  = blockIdx.y;
    const float* B  = by ? Wself : W;
    float*      Out = by ? outtmp : support;
    const int m0   = blockIdx.x * 128;
    const int tid  = threadIdx.x;
    const int wid  = tid >> 5;
    const int lane = tid & 31;
    const int wy   = wid & 3;        // row group (32 rows)
    const int wx   = wid >> 2;       // col group (64 cols)
    const int g    = lane >> 2;      // groupID
    const int tig  = lane & 3;       // thread in group

    float acc[2][8][4];
#pragma unroll
    for (int mt = 0; mt < 2; mt++)
#pragma unroll
        for (int nt = 0; nt < 8; nt++)
#pragma unroll
            for (int i = 0; i < 4; i++) acc[mt][nt][i] = 0.0f;

    for (int kc = 0; kc < DD; kc += 16) {
        // -- load A chunk (512 float4, 2 per thread) --
#pragma unroll
        for (int i = 0; i < 2; i++) {
            int idx = tid + i * 256;       // 0..511
            int row = idx >> 2;            // 0..127
            int kv  = (idx & 3) << 2;      // 0,4,8,12
            float4 v = make_float4(0.f, 0.f, 0.f, 0.f);
            int gr = m0 + row;
            if (gr < NN) v = *(const float4*)(A + (size_t)gr * DD + kc + kv);
            int rp   = ((row >> 4) << 3) + (row & 7);
            int half = (row >> 3) & 1;
            float* dst = (float*)As;
            dst[(rp * 20 + kv + 0) * 2 + half] = f2tf32(v.x);
            dst[(rp * 20 + kv + 1) * 2 + half] = f2tf32(v.y);
            dst[(rp * 20 + kv + 2) * 2 + half] = f2tf32(v.z);
            dst[(rp * 20 + kv + 3) * 2 + half] = f2tf32(v.w);
        }
        // -- load B chunk (16 k x 128 n = 512 float4, 2 per thread) --
#pragma unroll
        for (int i = 0; i < 2; i++) {
            int idx = tid + i * 256;
            int kl  = idx >> 5;            // 0..15
            int nv  = (idx & 31) << 2;     // 0..124
            float4 v = *(const float4*)(B + (size_t)(kc + kl) * DD + nv);
            int kp   = ((kl >> 3) << 2) | (kl & 3);
            int half = (kl >> 2) & 1;
            float* dst = (float*)Bs;
            dst[((nv + 0) * 20 + kp) * 2 + half] = f2tf32(v.x);
            dst[((nv + 1) * 20 + kp) * 2 + half] = f2tf32(v.y);
            dst[((nv + 2) * 20 + kp) * 2 + half] = f2tf32(v.z);
            dst[((nv + 3) * 20 + kp) * 2 + half] = f2tf32(v.w);
        }
        __syncthreads();

#pragma unroll
        for (int ks = 0; ks < 2; ks++) {
            uint32_t af[2][4];
#pragma unroll
            for (int mt = 0; mt < 2; mt++) {
                int rp = (wy * 2 + mt) * 8 + g;
                float2 p0 = As[rp * 20 + ks * 8 + tig];
                float2 p1 = As[rp * 20 + ks * 8 + tig + 4];
                af[mt][0] = __float_as_uint(p0.x);
                af[mt][1] = __float_as_uint(p0.y);
                af[mt][2] = __float_as_uint(p1.x);
                af[mt][3] = __float_as_uint(p1.y);
            }
            uint32_t bf[8][2];
#pragma unroll
            for (int nt = 0; nt < 8; nt++) {
                int n = wx * 64 + nt * 8 + g;
                float2 bp = Bs[n * 20 + ks * 4 + tig];
                bf[nt][0] = __float_as_uint(bp.x);
                bf[nt][1] = __float_as_uint(bp.y);
            }
#pragma unroll
            for (int mt = 0; mt < 2; mt++)
#pragma unroll
                for (int nt = 0; nt < 8; nt++)
                    mma_tf32(acc[mt][nt], af[mt], bf[nt]);
        }
        __syncthreads();
    }

    // -- epilogue --
#pragma unroll
    for (int nt = 0; nt < 8; nt++) {
        int col = wx * 64 + nt * 8 + (tig << 1);
        float2 bb = make_float2(0.f, 0.f);
        if (by) bb = *(const float2*)(bias + col);
#pragma unroll
        for (int mt = 0; mt < 2; mt++) {
            int r0 = m0 + wy * 32 + mt * 16 + g;
            if (r0 < NN) {
                float2 v0 = make_float2(acc[mt][nt][0] + bb.x, acc[mt][nt][1] + bb.y);
                *(float2*)(Out + (size_t)r0 * DD + col) = v0;
            }
            int r1 = r0 + 8;
            if (r1 < NN) {
                float2 v1 = make_float2(acc[mt][nt][2] + bb.x, acc[mt][nt][3] + bb.y);
                *(float2*)(Out + (size_t)r1 * DD + col) = v1;
            }
        }
    }
}

// ---------------- SpMM scatter: tmp[row] += val * support[col] --------------
__global__ __launch_bounds__(256) void spmm_scatter(
    const int* __restrict__ rows, const int* __restrict__ cols,
    const float* __restrict__ vals,
    const float* __restrict__ S, float* __restrict__ Out)
{
    int gid = blockIdx.x * blockDim.x + threadIdx.x;
    int e   = gid >> 5;
    if (e >= EADJ) return;
    int dg  = (gid & 31) << 2;
    int c   = cols[e];
    int r   = rows[e];
    float v = vals[e];
    float4 s = *(const float4*)(S + (size_t)c * DD + dg);
    float4 add = make_float4(v * s.x, v * s.y, v * s.z, v * s.w);
    atomicAdd((float4*)(Out + (size_t)r * DD + dg), add);
}

// ---------------- BN statistics ---------------------------------------------
__global__ void zero_stats()
{
    int t = threadIdx.x;
    if (t < 2 * DD) g_stats[t] = 0.0f;
}

__global__ __launch_bounds__(256) void col_stats2(const float* __restrict__ X)
{
    int w  = threadIdx.x >> 5;
    int l  = threadIdx.x & 31;
    int cg = l << 2;
    float4 s = make_float4(0.f, 0.f, 0.f, 0.f);
    float4 q = make_float4(0.f, 0.f, 0.f, 0.f);
    for (int r = blockIdx.x * 8 + w; r < NN; r += gridDim.x * 8) {
        float4 v = *(const float4*)(X + (size_t)r * DD + cg);
        s.x += v.x; s.y += v.y; s.z += v.z; s.w += v.w;
        q.x += v.x * v.x; q.y += v.y * v.y; q.z += v.z * v.z; q.w += v.w * v.w;
    }
    __shared__ float4 ss[8][32];
    __shared__ float4 qq[8][32];
    ss[w][l] = s;
    qq[w][l] = q;
    __syncthreads();
    if (w == 0) {
#pragma unroll
        for (int i = 1; i < 8; i++) {
            float4 a = ss[i][l], b = qq[i][l];
            s.x += a.x; s.y += a.y; s.z += a.z; s.w += a.w;
            q.x += b.x; q.y += b.y; q.z += b.z; q.w += b.w;
        }
        atomicAdd((float4*)&g_stats[cg], s);
        atomicAdd((float4*)&g_stats[DD + cg], q);
    }
}

// ---------------- BN normalize + ReLU ---------------------------------------
__global__ __launch_bounds__(256) void bn_relu(
    const float* __restrict__ X,
    const float* __restrict__ gamma,
    const float* __restrict__ beta,
    float* __restrict__ Hout)
{
    int gid = blockIdx.x * blockDim.x + threadIdx.x;
    if (gid >= NN * DD / 4) return;
    int col = (gid & 31) << 2;
    size_t off = (size_t)gid << 2;
    float4 v = *(const float4*)(X + off);
    const float invN = 1.0f / (float)NN;
    float4 r;
    {
        float m = g_stats[col + 0] * invN;
        float var = g_stats[DD + col + 0] * invN - m * m;
        r.x = fmaxf(0.f, (v.x - m) * rsqrtf(var + BNEPS) * gamma[col + 0] + beta[col + 0]);
    }
    {
        float m = g_stats[col + 1] * invN;
        float var = g_stats[DD + col + 1] * invN - m * m;
        r.y = fmaxf(0.f, (v.y - m) * rsqrtf(var + BNEPS) * gamma[col + 1] + beta[col + 1]);
    }
    {
        float m = g_stats[col + 2] * invN;
        float var = g_stats[DD + col + 2] * invN - m * m;
        r.z = fmaxf(0.f, (v.z - m) * rsqrtf(var + BNEPS) * gamma[col + 2] + beta[col + 2]);
    }
    {
        float m = g_stats[col + 3] * invN;
        float var = g_stats[DD + col + 3] * invN - m * m;
        r.w = fmaxf(0.f, (v.w - m) * rsqrtf(var + BNEPS) * gamma[col + 3] + beta[col + 3]);
    }
    *(float4*)(Hout + off) = r;
}

// ---------------- per-node edge scores --------------------------------------
__global__ __launch_bounds__(256) void node_scores(
    const float* __restrict__ H,
    const float* __restrict__ X,
    const float* __restrict__ Wc)
{
    int warp = (blockIdx.x * blockDim.x + threadIdx.x) >> 5;
    int lane = threadIdx.x & 31;
    if (warp >= NN) return;
    size_t off = (size_t)warp * DD + (lane << 2);
    float4 h = *(const float4*)(H + off);
    float4 x = *(const float4*)(X + off);
    float4 w1 = *(const float4*)(Wc + (lane << 2));
    float4 w2 = *(const float4*)(Wc + DD + (lane << 2));
    float e0 = h.x + x.x, e1 = h.y + x.y, e2 = h.z + x.z, e3 = h.w + x.w;
    float s1 = e0 * w1.x + e1 * w1.y + e2 * w1.z + e3 * w1.w;
    float s2 = e0 * w2.x + e1 * w2.y + e2 * w2.z + e3 * w2.w;
#pragma unroll
    for (int o = 16; o; o >>= 1) {
        s1 += __shfl_xor_sync(0xFFFFFFFFu, s1, o);
        s2 += __shfl_xor_sync(0xFFFFFFFFu, s2, o);
    }
    if (lane == 0) {
        g_s1[warp] = s1;
        g_s2[warp] = s2;
    }
}

// ---------------- edge prediction -------------------------------------------
__global__ __launch_bounds__(256) void edge_pred(
    const int* __restrict__ ei,
    const float* __restrict__ bc,
    float* __restrict__ out)
{
    int e = blockIdx.x * blockDim.x + threadIdx.x;
    if (e >= EPRED) return;
    float z = g_s1[ei[e]] + g_s2[ei[e + EPRED]] + bc[0];
    out[e] = 1.0f / (1.0f + expf(-z));
}

// ---------------- launch ----------------------------------------------------
extern "C" void kernel_launch(void* const* d_in, const int* in_sizes, int n_in,
                              void* d_out, int out_size)
{
    const float* x       = (const float*)d_in[0];
    const int*   adj_row = (const int*)d_in[1];
    const int*   adj_col = (const int*)d_in[2];
    const float* adj_val = (const float*)d_in[3];
    const int*   eidx    = (const int*)d_in[4];
    const float* W       = (const float*)d_in[5];
    const float* Wself   = (const float*)d_in[6];
    const float* b       = (const float*)d_in[7];
    const float* gamma   = (const float*)d_in[8];
    const float* beta    = (const float*)d_in[9];
    const float* Wc      = (const float*)d_in[10];
    const float* bc      = (const float*)d_in[11];
    float* out           = (float*)d_out;

    float *support, *tmp, *h1, *h2;
    cudaGetSymbolAddress((void**)&support, g_support);
    cudaGetSymbolAddress((void**)&tmp,     g_tmp);
    cudaGetSymbolAddress((void**)&h1,      g_h1);
    cudaGetSymbolAddress((void**)&h2,      g_h2);

    const dim3 gemm_grid((NN + 127) / 128, 2);
    const int spmm_blocks = (EADJ * 32 + 255) / 256;
    const int bn_blocks   = (NN * DD / 4 + 255) / 256;

    const float* hin = x;
    float* houts[2] = { h1, h2 };
    for (int l = 0; l < 2; l++) {
        gemm_tc<<<gemm_grid, 256>>>(hin, W + l * DD * DD, Wself + l * DD * DD,
                                    b + l * DD, support, tmp);
        spmm_scatter<<<spmm_blocks, 256>>>(adj_row, adj_col, adj_val, support, tmp);
        zero_stats<<<1, 256>>>();
        col_stats2<<<512, 256>>>(tmp);
        bn_relu<<<bn_blocks, 256>>>(tmp, gamma + l * DD, beta + l * DD, houts[l]);
        hin = houts[l];
    }

    node_scores<<<(NN * 32 + 255) / 256, 256>>>(h2, x, Wc);
    edge_pred<<<(EPRED + 255) / 256, 256>>>(eidx, bc, out);
}

// round 3
// speedup vs baseline: 1.4736x; 1.4736x over previous
#include <cuda_runtime.h>
#include <math.h>
#include <stdint.h>

#define NN    50000
#define DD    128
#define EADJ  800000
#define EPRED 500000
#define BNEPS 1e-5f

// ---------------- scratch ----------------------------------------------------
__device__ float g_support[NN * DD];
__device__ float g_tmp[NN * DD];
__device__ float g_stats[2 * 2 * DD];      // [layer][sum(128) | sumsq(128)]
__device__ float g_s1[NN];
__device__ float g_s2[NN];
__device__ int   g_counts[NN];             // histogram, then cursor
__device__ int   g_rowstart[NN + 1];
__device__ int   g_cursor[NN];
__device__ int   g_csr_col[EADJ];
__device__ float g_csr_val[EADJ];

// ---------------- helpers ----------------------------------------------------
__device__ __forceinline__ float f2tf32(float f) {
    uint32_t r;
    asm("cvt.rna.tf32.f32 %0, %1;" : "=r"(r) : "f"(f));
    return __uint_as_float(r);
}

__device__ __forceinline__ void mma_tf32(float* c, const uint32_t* a, const uint32_t* b) {
    asm volatile(
        "mma.sync.aligned.m16n8k8.row.col.f32.tf32.tf32.f32 "
        "{%0,%1,%2,%3}, {%4,%5,%6,%7}, {%8,%9}, {%0,%1,%2,%3};\n"
        : "+f"(c[0]), "+f"(c[1]), "+f"(c[2]), "+f"(c[3])
        : "r"(a[0]), "r"(a[1]), "r"(a[2]), "r"(a[3]), "r"(b[0]), "r"(b[1]));
}

__device__ __forceinline__ float bn_one(float v, const float* st, const float* gm,
                                        const float* be, int col) {
    const float invN = 1.0f / (float)NN;
    float m   = st[col] * invN;
    float var = st[DD + col] * invN - m * m;
    return fmaxf(0.f, (v - m) * rsqrtf(var + BNEPS) * gm[col] + be[col]);
}

// ---------------- tf32 tensor-core dual GEMM --------------------------------
// Tile 128x128, K-chunk 32. smem stride 36 words -> all fragment LDS and all
// STS patterns are bank-conflict-free (bank = 4g + tig, distinct over warp).
// grid.y: 0 -> support = A@W ; 1 -> tmp = A@Wself + bias
// Optional BN+ReLU applied to A on load (layer-2 input fusion).
__global__ __launch_bounds__(256, 2) void gemm_tc(
    const float* __restrict__ A,
    const float* __restrict__ W,
    const float* __restrict__ Wself,
    const float* __restrict__ bias,
    const float* __restrict__ bn_st,    // null -> no BN on A
    const float* __restrict__ bn_gm,
    const float* __restrict__ bn_be,
    float* __restrict__ support,
    float* __restrict__ outtmp)
{
    __shared__ float As[128 * 36];
    __shared__ float Bs[128 * 36];

    const int   by  = blockIdx.y;
    const float* B  = by ? Wself : W;
    float*      Out = by ? outtmp : support;
    const int m0   = blockIdx.x * 128;
    const int tid  = threadIdx.x;
    const int wid  = tid >> 5;
    const int lane = tid & 31;
    const int wy   = wid & 3;        // 32-row slice
    const int wx   = wid >> 2;       // 64-col slice
    const int g    = lane >> 2;
    const int tig  = lane & 3;

    float acc[2][8][4];
#pragma unroll
    for (int mt = 0; mt < 2; mt++)
#pragma unroll
        for (int nt = 0; nt < 8; nt++)
#pragma unroll
            for (int i = 0; i < 4; i++) acc[mt][nt][i] = 0.0f;

    for (int kc = 0; kc < DD; kc += 32) {
        // ---- A chunk: 128 rows x 32 k, float4 stores, conflict-free ----
#pragma unroll
        for (int i = 0; i < 4; i++) {
            int idx = tid + i * 256;          // 0..1023
            int row = idx >> 3;               // 0..127
            int kv  = (idx & 7) << 2;         // 0..28
            float4 v = make_float4(0.f, 0.f, 0.f, 0.f);
            int gr = m0 + row;
            if (gr < NN) v = *(const float4*)(A + (size_t)gr * DD + kc + kv);
            if (bn_st) {
                v.x = bn_one(v.x, bn_st, bn_gm, bn_be, kc + kv + 0);
                v.y = bn_one(v.y, bn_st, bn_gm, bn_be, kc + kv + 1);
                v.z = bn_one(v.z, bn_st, bn_gm, bn_be, kc + kv + 2);
                v.w = bn_one(v.w, bn_st, bn_gm, bn_be, kc + kv + 3);
            }
            float4 t;
            t.x = f2tf32(v.x); t.y = f2tf32(v.y);
            t.z = f2tf32(v.z); t.w = f2tf32(v.w);
            *(float4*)(&As[row * 36 + kv]) = t;
        }
        // ---- B chunk: transpose to Bs[n][k]; lane->k so banks distinct ----
#pragma unroll
        for (int i = 0; i < 4; i++) {
            int k  = lane;                             // 0..31
            int n0 = ((tid >> 5) + i * 8) << 2;        // 0..124
            float4 v = *(const float4*)(B + (size_t)(kc + k) * DD + n0);
            Bs[(n0 + 0) * 36 + k] = f2tf32(v.x);
            Bs[(n0 + 1) * 36 + k] = f2tf32(v.y);
            Bs[(n0 + 2) * 36 + k] = f2tf32(v.z);
            Bs[(n0 + 3) * 36 + k] = f2tf32(v.w);
        }
        __syncthreads();

#pragma unroll
        for (int ks = 0; ks < 4; ks++) {
            int kk = ks * 8 + tig;
            uint32_t af[2][4];
#pragma unroll
            for (int mt = 0; mt < 2; mt++) {
                int rb = wy * 32 + mt * 16;
                af[mt][0] = __float_as_uint(As[(rb + g) * 36 + kk]);
                af[mt][1] = __float_as_uint(As[(rb + g + 8) * 36 + kk]);
                af[mt][2] = __float_as_uint(As[(rb + g) * 36 + kk + 4]);
                af[mt][3] = __float_as_uint(As[(rb + g + 8) * 36 + kk + 4]);
            }
            uint32_t bf[8][2];
#pragma unroll
            for (int nt = 0; nt < 8; nt++) {
                int n = wx * 64 + nt * 8 + g;
                bf[nt][0] = __float_as_uint(Bs[n * 36 + kk]);
                bf[nt][1] = __float_as_uint(Bs[n * 36 + kk + 4]);
            }
#pragma unroll
            for (int mt = 0; mt < 2; mt++)
#pragma unroll
                for (int nt = 0; nt < 8; nt++)
                    mma_tf32(acc[mt][nt], af[mt], bf[nt]);
        }
        __syncthreads();
    }

    // ---- epilogue ----
#pragma unroll
    for (int nt = 0; nt < 8; nt++) {
        int col = wx * 64 + nt * 8 + (tig << 1);
        float2 bb = make_float2(0.f, 0.f);
        if (by) bb = *(const float2*)(bias + col);
#pragma unroll
        for (int mt = 0; mt < 2; mt++) {
            int r0 = m0 + wy * 32 + mt * 16 + g;
            if (r0 < NN) {
                float2 v0 = make_float2(acc[mt][nt][0] + bb.x, acc[mt][nt][1] + bb.y);
                *(float2*)(Out + (size_t)r0 * DD + col) = v0;
            }
            int r1 = r0 + 8;
            if (r1 < NN) {
                float2 v1 = make_float2(acc[mt][nt][2] + bb.x, acc[mt][nt][3] + bb.y);
                *(float2*)(Out + (size_t)r1 * DD + col) = v1;
            }
        }
    }
}

// ---------------- CSR build ---------------------------------------------------
__global__ __launch_bounds__(512) void init_zero()
{
    int i = blockIdx.x * blockDim.x + threadIdx.x;
    if (i < NN) g_counts[i] = 0;
    if (i < 2 * 2 * DD) g_stats[i] = 0.f;
}

__global__ __launch_bounds__(256) void histo(const int* __restrict__ rows)
{
    int e = blockIdx.x * blockDim.x + threadIdx.x;
    if (e < EADJ) atomicAdd(&g_counts[rows[e]], 1);
}

__global__ __launch_bounds__(1024) void scan_rows()
{
    __shared__ int wsum[32];
    __shared__ int carry;
    int tid = threadIdx.x, lane = tid & 31, wid = tid >> 5;
    if (tid == 0) carry = 0;
    __syncthreads();
    for (int base = 0; base < NN; base += 1024) {
        int i = base + tid;
        int v = (i < NN) ? g_counts[i] : 0;
        int inc = v;
#pragma unroll
        for (int o = 1; o < 32; o <<= 1) {
            int n = __shfl_up_sync(0xFFFFFFFFu, inc, o);
            if (lane >= o) inc += n;
        }
        if (lane == 31) wsum[wid] = inc;
        __syncthreads();
        if (wid == 0) {
            int ws = wsum[lane];
#pragma unroll
            for (int o = 1; o < 32; o <<= 1) {
                int n = __shfl_up_sync(0xFFFFFFFFu, ws, o);
                if (lane >= o) ws += n;
            }
            wsum[lane] = ws;
        }
        __syncthreads();
        int wpre = wid ? wsum[wid - 1] : 0;
        int excl = carry + wpre + inc - v;
        if (i < NN) { g_rowstart[i] = excl; g_cursor[i] = excl; }
        __syncthreads();
        if (tid == 0) carry += wsum[31];
        __syncthreads();
    }
    if (tid == 0) g_rowstart[NN] = carry;
}

__global__ __launch_bounds__(256) void scatter_csr(
    const int* __restrict__ rows, const int* __restrict__ cols,
    const float* __restrict__ vals)
{
    int e = blockIdx.x * blockDim.x + threadIdx.x;
    if (e >= EADJ) return;
    int p = atomicAdd(&g_cursor[rows[e]], 1);
    g_csr_col[p] = cols[e];
    g_csr_val[p] = vals[e];
}

// ---------------- CSR SpMM: Out[row] += sum val * S[col] ---------------------
__global__ __launch_bounds__(256) void spmm_csr(
    const float* __restrict__ S, float* __restrict__ Out)
{
    int row  = blockIdx.x * 8 + (threadIdx.x >> 5);
    int lane = threadIdx.x & 31;
    if (row >= NN) return;
    int s = g_rowstart[row];
    int e = g_rowstart[row + 1];
    float4 acc = make_float4(0.f, 0.f, 0.f, 0.f);
    for (int base = s; base < e; base += 32) {
        int idx = base + lane;
        int   c = (idx < e) ? g_csr_col[idx] : 0;
        float v = (idx < e) ? g_csr_val[idx] : 0.f;
        int cnt = e - base; if (cnt > 32) cnt = 32;
        for (int i = 0; i < cnt; i++) {
            int   cc = __shfl_sync(0xFFFFFFFFu, c, i);
            float vv = __shfl_sync(0xFFFFFFFFu, v, i);
            float4 sv = *(const float4*)(S + (size_t)cc * DD + (lane << 2));
            acc.x += vv * sv.x; acc.y += vv * sv.y;
            acc.z += vv * sv.z; acc.w += vv * sv.w;
        }
    }
    float4* p = (float4*)(Out + (size_t)row * DD + (lane << 2));
    float4 t = *p;
    t.x += acc.x; t.y += acc.y; t.z += acc.z; t.w += acc.w;
    *p = t;
}

// ---------------- BN statistics ----------------------------------------------
__global__ __launch_bounds__(256) void col_stats2(const float* __restrict__ X,
                                                  float* __restrict__ stats)
{
    int w  = threadIdx.x >> 5;
    int l  = threadIdx.x & 31;
    int cg = l << 2;
    const int T = gridDim.x * 8;
    float4 s = make_float4(0.f, 0.f, 0.f, 0.f);
    float4 q = make_float4(0.f, 0.f, 0.f, 0.f);
    for (int r = blockIdx.x * 8 + w; r < NN; r += 4 * T) {
#pragma unroll
        for (int i = 0; i < 4; i++) {
            int rr = r + i * T;
            if (rr < NN) {
                float4 v = *(const float4*)(X + (size_t)rr * DD + cg);
                s.x += v.x; s.y += v.y; s.z += v.z; s.w += v.w;
                q.x += v.x * v.x; q.y += v.y * v.y;
                q.z += v.z * v.z; q.w += v.w * v.w;
            }
        }
    }
    __shared__ float4 ss[8][32];
    __shared__ float4 qq[8][32];
    ss[w][l] = s;
    qq[w][l] = q;
    __syncthreads();
    if (w == 0) {
#pragma unroll
        for (int i = 1; i < 8; i++) {
            float4 a = ss[i][l], b = qq[i][l];
            s.x += a.x; s.y += a.y; s.z += a.z; s.w += a.w;
            q.x += b.x; q.y += b.y; q.z += b.z; q.w += b.w;
        }
        atomicAdd((float*)&stats[cg + 0], s.x);
        atomicAdd((float*)&stats[cg + 1], s.y);
        atomicAdd((float*)&stats[cg + 2], s.z);
        atomicAdd((float*)&stats[cg + 3], s.w);
        atomicAdd((float*)&stats[DD + cg + 0], q.x);
        atomicAdd((float*)&stats[DD + cg + 1], q.y);
        atomicAdd((float*)&stats[DD + cg + 2], q.z);
        atomicAdd((float*)&stats[DD + cg + 3], q.w);
    }
}

// ---------------- node scores (BN of layer2 fused in) ------------------------
__global__ __launch_bounds__(256) void node_scores(
    const float* __restrict__ T2,      // tmp of layer 2 (pre-BN)
    const float* __restrict__ st,      // stats of layer 2
    const float* __restrict__ gm,
    const float* __restrict__ be,
    const float* __restrict__ X,
    const float* __restrict__ Wc)
{
    int warp = (blockIdx.x * blockDim.x + threadIdx.x) >> 5;
    int lane = threadIdx.x & 31;
    if (warp >= NN) return;
    int cg = lane << 2;
    size_t off = (size_t)warp * DD + cg;
    float4 t = *(const float4*)(T2 + off);
    float4 x = *(const float4*)(X + off);
    float h0 = bn_one(t.x, st, gm, be, cg + 0) + x.x;
    float h1 = bn_one(t.y, st, gm, be, cg + 1) + x.y;
    float h2 = bn_one(t.z, st, gm, be, cg + 2) + x.z;
    float h3 = bn_one(t.w, st, gm, be, cg + 3) + x.w;
    float4 w1 = *(const float4*)(Wc + cg);
    float4 w2 = *(const float4*)(Wc + DD + cg);
    float s1 = h0 * w1.x + h1 * w1.y + h2 * w1.z + h3 * w1.w;
    float s2 = h0 * w2.x + h1 * w2.y + h2 * w2.z + h3 * w2.w;
#pragma unroll
    for (int o = 16; o; o >>= 1) {
        s1 += __shfl_xor_sync(0xFFFFFFFFu, s1, o);
        s2 += __shfl_xor_sync(0xFFFFFFFFu, s2, o);
    }
    if (lane == 0) {
        g_s1[warp] = s1;
        g_s2[warp] = s2;
    }
}

// ---------------- edge prediction --------------------------------------------
__global__ __launch_bounds__(256) void edge_pred(
    const int* __restrict__ ei,
    const float* __restrict__ bc,
    float* __restrict__ out)
{
    int e = blockIdx.x * blockDim.x + threadIdx.x;
    if (e >= EPRED) return;
    float z = g_s1[ei[e]] + g_s2[ei[e + EPRED]] + bc[0];
    out[e] = 1.0f / (1.0f + expf(-z));
}

// ---------------- launch ------------------------------------------------------
extern "C" void kernel_launch(void* const* d_in, const int* in_sizes, int n_in,
                              void* d_out, int out_size)
{
    const float* x       = (const float*)d_in[0];
    const int*   adj_row = (const int*)d_in[1];
    const int*   adj_col = (const int*)d_in[2];
    const float* adj_val = (const float*)d_in[3];
    const int*   eidx    = (const int*)d_in[4];
    const float* W       = (const float*)d_in[5];
    const float* Wself   = (const float*)d_in[6];
    const float* b       = (const float*)d_in[7];
    const float* gamma   = (const float*)d_in[8];
    const float* beta    = (const float*)d_in[9];
    const float* Wc      = (const float*)d_in[10];
    const float* bc      = (const float*)d_in[11];
    float* out           = (float*)d_out;

    float *support, *tmp, *stats;
    cudaGetSymbolAddress((void**)&support, g_support);
    cudaGetSymbolAddress((void**)&tmp,     g_tmp);
    cudaGetSymbolAddress((void**)&stats,   g_stats);

    const dim3 gemm_grid((NN + 127) / 128, 2);
    const int eb = (EADJ + 255) / 256;

    // CSR build (adjacency identical across both layers)
    init_zero<<<(NN + 511) / 512, 512>>>();
    histo<<<eb, 256>>>(adj_row);
    scan_rows<<<1, 1024>>>();
    scatter_csr<<<eb, 256>>>(adj_row, adj_col, adj_val);

    // layer 1: A = x (no BN)
    gemm_tc<<<gemm_grid, 256>>>(x, W, Wself, b, nullptr, nullptr, nullptr,
                                support, tmp);
    spmm_csr<<<(NN + 7) / 8, 256>>>(support, tmp);
    col_stats2<<<512, 256>>>(tmp, stats);

    // layer 2: A = relu(bn(tmp1)) fused into the A-load
    gemm_tc<<<gemm_grid, 256>>>(tmp, W + DD * DD, Wself + DD * DD, b + DD,
                                stats, gamma, beta, support, tmp);
    spmm_csr<<<(NN + 7) / 8, 256>>>(support, tmp);
    col_stats2<<<512, 256>>>(tmp, stats + 2 * DD);

    node_scores<<<(NN * 32 + 255) / 256, 256>>>(tmp, stats + 2 * DD,
                                                gamma + DD, beta + DD, x, Wc);
    edge_pred<<<(EPRED + 255) / 256, 256>>>(eidx, bc, out);
}

// round 4
// speedup vs baseline: 1.8276x; 1.2402x over previous
#include <cuda_runtime.h>
#include <math.h>
#include <stdint.h>

#define NN    50000
#define DD    128
#define EADJ  800000
#define EPRED 500000
#define BNEPS 1e-5f
#define SCANB 196          // ceil(NN/256)
#define NCOPY 32           // stat partial copies

// ---------------- scratch ----------------------------------------------------
__device__ float g_support[NN * DD];
__device__ float g_tmp[NN * DD];
__device__ float g_stats[2 * 2 * DD];          // [layer][sum|sumsq]
__device__ float g_statpart[2 * NCOPY * 2 * DD];
__device__ float g_s1[NN];
__device__ float g_s2[NN];
__device__ int   g_counts[NN];
__device__ int   g_rowstart[NN + 1];
__device__ int   g_cursor[NN];
__device__ int   g_blocksum[SCANB];
__device__ int   g_blockoff[SCANB];
__device__ int2  g_csr[EADJ];                  // (col, val-bits) interleaved

// ---------------- helpers ----------------------------------------------------
__device__ __forceinline__ float f2tf32(float f) {
    uint32_t r;
    asm("cvt.rna.tf32.f32 %0, %1;" : "=r"(r) : "f"(f));
    return __uint_as_float(r);
}

__device__ __forceinline__ void mma_tf32(float* c, const uint32_t* a, const uint32_t* b) {
    asm volatile(
        "mma.sync.aligned.m16n8k8.row.col.f32.tf32.tf32.f32 "
        "{%0,%1,%2,%3}, {%4,%5,%6,%7}, {%8,%9}, {%0,%1,%2,%3};\n"
        : "+f"(c[0]), "+f"(c[1]), "+f"(c[2]), "+f"(c[3])
        : "r"(a[0]), "r"(a[1]), "r"(a[2]), "r"(a[3]), "r"(b[0]), "r"(b[1]));
}

__device__ __forceinline__ float bn_one(float v, const float* st, const float* gm,
                                        const float* be, int col) {
    const float invN = 1.0f / (float)NN;
    float m   = st[col] * invN;
    float var = st[DD + col] * invN - m * m;
    return fmaxf(0.f, (v - m) * rsqrtf(var + BNEPS) * gm[col] + be[col]);
}

// ---------------- tf32 tensor-core dual GEMM --------------------------------
__global__ __launch_bounds__(256, 2) void gemm_tc(
    const float* __restrict__ A,
    const float* __restrict__ W,
    const float* __restrict__ Wself,
    const float* __restrict__ bias,
    const float* __restrict__ bn_st,
    const float* __restrict__ bn_gm,
    const float* __restrict__ bn_be,
    float* __restrict__ support,
    float* __restrict__ outtmp)
{
    __shared__ float As[128 * 36];
    __shared__ float Bs[128 * 36];

    const int   by  = blockIdx.y;
    const float* B  = by ? Wself : W;
    float*      Out = by ? outtmp : support;
    const int m0   = blockIdx.x * 128;
    const int tid  = threadIdx.x;
    const int wid  = tid >> 5;
    const int lane = tid & 31;
    const int wy   = wid & 3;
    const int wx   = wid >> 2;
    const int g    = lane >> 2;
    const int tig  = lane & 3;

    float acc[2][8][4];
#pragma unroll
    for (int mt = 0; mt < 2; mt++)
#pragma unroll
        for (int nt = 0; nt < 8; nt++)
#pragma unroll
            for (int i = 0; i < 4; i++) acc[mt][nt][i] = 0.0f;

    for (int kc = 0; kc < DD; kc += 32) {
#pragma unroll
        for (int i = 0; i < 4; i++) {
            int idx = tid + i * 256;
            int row = idx >> 3;
            int kv  = (idx & 7) << 2;
            float4 v = make_float4(0.f, 0.f, 0.f, 0.f);
            int gr = m0 + row;
            if (gr < NN) v = *(const float4*)(A + (size_t)gr * DD + kc + kv);
            if (bn_st) {
                v.x = bn_one(v.x, bn_st, bn_gm, bn_be, kc + kv + 0);
                v.y = bn_one(v.y, bn_st, bn_gm, bn_be, kc + kv + 1);
                v.z = bn_one(v.z, bn_st, bn_gm, bn_be, kc + kv + 2);
                v.w = bn_one(v.w, bn_st, bn_gm, bn_be, kc + kv + 3);
            }
            float4 t;
            t.x = f2tf32(v.x); t.y = f2tf32(v.y);
            t.z = f2tf32(v.z); t.w = f2tf32(v.w);
            *(float4*)(&As[row * 36 + kv]) = t;
        }
#pragma unroll
        for (int i = 0; i < 4; i++) {
            int k  = lane;
            int n0 = ((tid >> 5) + i * 8) << 2;
            float4 v = *(const float4*)(B + (size_t)(kc + k) * DD + n0);
            Bs[(n0 + 0) * 36 + k] = f2tf32(v.x);
            Bs[(n0 + 1) * 36 + k] = f2tf32(v.y);
            Bs[(n0 + 2) * 36 + k] = f2tf32(v.z);
            Bs[(n0 + 3) * 36 + k] = f2tf32(v.w);
        }
        __syncthreads();

#pragma unroll
        for (int ks = 0; ks < 4; ks++) {
            int kk = ks * 8 + tig;
            uint32_t af[2][4];
#pragma unroll
            for (int mt = 0; mt < 2; mt++) {
                int rb = wy * 32 + mt * 16;
                af[mt][0] = __float_as_uint(As[(rb + g) * 36 + kk]);
                af[mt][1] = __float_as_uint(As[(rb + g + 8) * 36 + kk]);
                af[mt][2] = __float_as_uint(As[(rb + g) * 36 + kk + 4]);
                af[mt][3] = __float_as_uint(As[(rb + g + 8) * 36 + kk + 4]);
            }
            uint32_t bf[8][2];
#pragma unroll
            for (int nt = 0; nt < 8; nt++) {
                int n = wx * 64 + nt * 8 + g;
                bf[nt][0] = __float_as_uint(Bs[n * 36 + kk]);
                bf[nt][1] = __float_as_uint(Bs[n * 36 + kk + 4]);
            }
#pragma unroll
            for (int mt = 0; mt < 2; mt++)
#pragma unroll
                for (int nt = 0; nt < 8; nt++)
                    mma_tf32(acc[mt][nt], af[mt], bf[nt]);
        }
        __syncthreads();
    }

#pragma unroll
    for (int nt = 0; nt < 8; nt++) {
        int col = wx * 64 + nt * 8 + (tig << 1);
        float2 bb = make_float2(0.f, 0.f);
        if (by) bb = *(const float2*)(bias + col);
#pragma unroll
        for (int mt = 0; mt < 2; mt++) {
            int r0 = m0 + wy * 32 + mt * 16 + g;
            if (r0 < NN) {
                float2 v0 = make_float2(acc[mt][nt][0] + bb.x, acc[mt][nt][1] + bb.y);
                *(float2*)(Out + (size_t)r0 * DD + col) = v0;
            }
            int r1 = r0 + 8;
            if (r1 < NN) {
                float2 v1 = make_float2(acc[mt][nt][2] + bb.x, acc[mt][nt][3] + bb.y);
                *(float2*)(Out + (size_t)r1 * DD + col) = v1;
            }
        }
    }
}

// ---------------- CSR build ---------------------------------------------------
__global__ __launch_bounds__(512) void init_zero()
{
    int i = blockIdx.x * blockDim.x + threadIdx.x;
    if (i < NN) g_counts[i] = 0;
    if (i < 2 * NCOPY * 2 * DD) g_statpart[i] = 0.f;
}

__global__ __launch_bounds__(256) void histo(const int* __restrict__ rows)
{
    int e = blockIdx.x * blockDim.x + threadIdx.x;
    if (e < EADJ) atomicAdd(&g_counts[rows[e]], 1);
}

// block sums of counts
__global__ __launch_bounds__(256) void scan_partial()
{
    __shared__ int ws[8];
    int tid = threadIdx.x, lane = tid & 31, w = tid >> 5;
    int i = blockIdx.x * 256 + tid;
    int v = (i < NN) ? g_counts[i] : 0;
    int s = v;
#pragma unroll
    for (int o = 16; o; o >>= 1) s += __shfl_xor_sync(0xFFFFFFFFu, s, o);
    if (lane == 0) ws[w] = s;
    __syncthreads();
    if (tid == 0) {
        int t = 0;
#pragma unroll
        for (int k = 0; k < 8; k++) t += ws[k];
        g_blocksum[blockIdx.x] = t;
    }
}

// exclusive scan of 196 block sums (single block)
__global__ __launch_bounds__(256) void scan_blocksums()
{
    __shared__ int ws[8];
    int t = threadIdx.x, lane = t & 31, w = t >> 5;
    int v = (t < SCANB) ? g_blocksum[t] : 0;
    int inc = v;
#pragma unroll
    for (int o = 1; o < 32; o <<= 1) {
        int n = __shfl_up_sync(0xFFFFFFFFu, inc, o);
        if (lane >= o) inc += n;
    }
    if (lane == 31) ws[w] = inc;
    __syncthreads();
    if (w == 0 && lane < 8) {
        int s = ws[lane];
#pragma unroll
        for (int o = 1; o < 8; o <<= 1) {
            int n = __shfl_up_sync(0xFFu, s, o);
            if (lane >= o) s += n;
        }
        ws[lane] = s;
    }
    __syncthreads();
    int off = w ? ws[w - 1] : 0;
    if (t < SCANB) g_blockoff[t] = off + inc - v;   // exclusive
}

// local exclusive scan + block offset -> rowstart, cursor
__global__ __launch_bounds__(256) void scan_apply()
{
    __shared__ int ws[8];
    int tid = threadIdx.x, lane = tid & 31, w = tid >> 5;
    int i = blockIdx.x * 256 + tid;
    int v = (i < NN) ? g_counts[i] : 0;
    int inc = v;
#pragma unroll
    for (int o = 1; o < 32; o <<= 1) {
        int n = __shfl_up_sync(0xFFFFFFFFu, inc, o);
        if (lane >= o) inc += n;
    }
    if (lane == 31) ws[w] = inc;
    __syncthreads();
    if (w == 0 && lane < 8) {
        int s = ws[lane];
#pragma unroll
        for (int o = 1; o < 8; o <<= 1) {
            int n = __shfl_up_sync(0xFFu, s, o);
            if (lane >= o) s += n;
        }
        ws[lane] = s;
    }
    __syncthreads();
    int excl = g_blockoff[blockIdx.x] + (w ? ws[w - 1] : 0) + inc - v;
    if (i < NN) { g_rowstart[i] = excl; g_cursor[i] = excl; }
    if (i == 0) g_rowstart[NN] = EADJ;
}

__global__ __launch_bounds__(256) void scatter_csr(
    const int* __restrict__ rows, const int* __restrict__ cols,
    const float* __restrict__ vals)
{
    int e = blockIdx.x * blockDim.x + threadIdx.x;
    if (e >= EADJ) return;
    int p = atomicAdd(&g_cursor[rows[e]], 1);
    g_csr[p] = make_int2(cols[e], __float_as_int(vals[e]));
}

// ---------------- CSR SpMM + fused BN stats ----------------------------------
// 256 threads = 8 warps; warp handles 4 rows; block covers 32 rows.
// stats accumulated into sliced partial copies to dodge atomic contention.
__global__ __launch_bounds__(256) void spmm_csr(
    const float* __restrict__ S, float* __restrict__ Out,
    float* __restrict__ statpart)
{
    int lane = threadIdx.x & 31;
    int w    = threadIdx.x >> 5;
    int cg   = lane << 2;

    float4 s = make_float4(0.f, 0.f, 0.f, 0.f);
    float4 q = make_float4(0.f, 0.f, 0.f, 0.f);

#pragma unroll
    for (int r4 = 0; r4 < 4; r4++) {
        int row = blockIdx.x * 32 + w * 4 + r4;
        if (row >= NN) break;
        int e0 = g_rowstart[row];
        int e1 = g_rowstart[row + 1];
        float4 acc = make_float4(0.f, 0.f, 0.f, 0.f);
        int i = e0;
        for (; i + 4 <= e1; i += 4) {
            int2 cv0 = g_csr[i + 0];
            int2 cv1 = g_csr[i + 1];
            int2 cv2 = g_csr[i + 2];
            int2 cv3 = g_csr[i + 3];
            float4 s0 = *(const float4*)(S + (size_t)cv0.x * DD + cg);
            float4 s1 = *(const float4*)(S + (size_t)cv1.x * DD + cg);
            float4 s2 = *(const float4*)(S + (size_t)cv2.x * DD + cg);
            float4 s3 = *(const float4*)(S + (size_t)cv3.x * DD + cg);
            float v0 = __int_as_float(cv0.y), v1 = __int_as_float(cv1.y);
            float v2 = __int_as_float(cv2.y), v3 = __int_as_float(cv3.y);
            acc.x += v0 * s0.x + v1 * s1.x + v2 * s2.x + v3 * s3.x;
            acc.y += v0 * s0.y + v1 * s1.y + v2 * s2.y + v3 * s3.y;
            acc.z += v0 * s0.z + v1 * s1.z + v2 * s2.z + v3 * s3.z;
            acc.w += v0 * s0.w + v1 * s1.w + v2 * s2.w + v3 * s3.w;
        }
        for (; i < e1; i++) {
            int2 cv = g_csr[i];
            float vv = __int_as_float(cv.y);
            float4 sv = *(const float4*)(S + (size_t)cv.x * DD + cg);
            acc.x += vv * sv.x; acc.y += vv * sv.y;
            acc.z += vv * sv.z; acc.w += vv * sv.w;
        }
        float4* p = (float4*)(Out + (size_t)row * DD + cg);
        float4 t = *p;
        t.x += acc.x; t.y += acc.y; t.z += acc.z; t.w += acc.w;
        *p = t;
        s.x += t.x; s.y += t.y; s.z += t.z; s.w += t.w;
        q.x += t.x * t.x; q.y += t.y * t.y;
        q.z += t.z * t.z; q.w += t.w * t.w;
    }

    __shared__ float4 ss[8][32];
    __shared__ float4 qq[8][32];
    ss[w][lane] = s;
    qq[w][lane] = q;
    __syncthreads();
    if (w == 0) {
#pragma unroll
        for (int k = 1; k < 8; k++) {
            float4 a = ss[k][lane], b = qq[k][lane];
            s.x += a.x; s.y += a.y; s.z += a.z; s.w += a.w;
            q.x += b.x; q.y += b.y; q.z += b.z; q.w += b.w;
        }
        float* base = statpart + (size_t)(blockIdx.x & (NCOPY - 1)) * 2 * DD;
        atomicAdd((float4*)(base + cg), s);
        atomicAdd((float4*)(base + DD + cg), q);
    }
}

// fold NCOPY partial copies into stats
__global__ __launch_bounds__(256) void reduce_stats(
    const float* __restrict__ statpart, float* __restrict__ stats)
{
    int t = threadIdx.x;          // 0..255
    float a = 0.f;
#pragma unroll
    for (int c = 0; c < NCOPY; c++) a += statpart[c * 2 * DD + t];
    stats[t] = a;
}

// ---------------- node scores (BN of layer2 fused) ----------------------------
__global__ __launch_bounds__(256) void node_scores(
    const float* __restrict__ T2,
    const float* __restrict__ st,
    const float* __restrict__ gm,
    const float* __restrict__ be,
    const float* __restrict__ X,
    const float* __restrict__ Wc)
{
    int warp = (blockIdx.x * blockDim.x + threadIdx.x) >> 5;
    int lane = threadIdx.x & 31;
    if (warp >= NN) return;
    int cg = lane << 2;
    size_t off = (size_t)warp * DD + cg;
    float4 t = *(const float4*)(T2 + off);
    float4 x = *(const float4*)(X + off);
    float h0 = bn_one(t.x, st, gm, be, cg + 0) + x.x;
    float h1 = bn_one(t.y, st, gm, be, cg + 1) + x.y;
    float h2 = bn_one(t.z, st, gm, be, cg + 2) + x.z;
    float h3 = bn_one(t.w, st, gm, be, cg + 3) + x.w;
    float4 w1 = *(const float4*)(Wc + cg);
    float4 w2 = *(const float4*)(Wc + DD + cg);
    float s1 = h0 * w1.x + h1 * w1.y + h2 * w1.z + h3 * w1.w;
    float s2 = h0 * w2.x + h1 * w2.y + h2 * w2.z + h3 * w2.w;
#pragma unroll
    for (int o = 16; o; o >>= 1) {
        s1 += __shfl_xor_sync(0xFFFFFFFFu, s1, o);
        s2 += __shfl_xor_sync(0xFFFFFFFFu, s2, o);
    }
    if (lane == 0) {
        g_s1[warp] = s1;
        g_s2[warp] = s2;
    }
}

// ---------------- edge prediction ---------------------------------------------
__global__ __launch_bounds__(256) void edge_pred(
    const int* __restrict__ ei,
    const float* __restrict__ bc,
    float* __restrict__ out)
{
    int e = blockIdx.x * blockDim.x + threadIdx.x;
    if (e >= EPRED) return;
    float z = g_s1[ei[e]] + g_s2[ei[e + EPRED]] + bc[0];
    out[e] = 1.0f / (1.0f + expf(-z));
}

// ---------------- launch ------------------------------------------------------
extern "C" void kernel_launch(void* const* d_in, const int* in_sizes, int n_in,
                              void* d_out, int out_size)
{
    const float* x       = (const float*)d_in[0];
    const int*   adj_row = (const int*)d_in[1];
    const int*   adj_col = (const int*)d_in[2];
    const float* adj_val = (const float*)d_in[3];
    const int*   eidx    = (const int*)d_in[4];
    const float* W       = (const float*)d_in[5];
    const float* Wself   = (const float*)d_in[6];
    const float* b       = (const float*)d_in[7];
    const float* gamma   = (const float*)d_in[8];
    const float* beta    = (const float*)d_in[9];
    const float* Wc      = (const float*)d_in[10];
    const float* bc      = (const float*)d_in[11];
    float* out           = (float*)d_out;

    float *support, *tmp, *stats, *statpart;
    cudaGetSymbolAddress((void**)&support,  g_support);
    cudaGetSymbolAddress((void**)&tmp,      g_tmp);
    cudaGetSymbolAddress((void**)&stats,    g_stats);
    cudaGetSymbolAddress((void**)&statpart, g_statpart);

    const dim3 gemm_grid((NN + 127) / 128, 2);
    const int eb = (EADJ + 255) / 256;
    const int spmm_blocks = (NN + 31) / 32;

    // CSR build
    init_zero<<<(2 * NCOPY * 2 * DD > NN ? 2 * NCOPY * 2 * DD : NN) / 512 + 1, 512>>>();
    histo<<<eb, 256>>>(adj_row);
    scan_partial<<<SCANB, 256>>>();
    scan_blocksums<<<1, 256>>>();
    scan_apply<<<SCANB, 256>>>();
    scatter_csr<<<eb, 256>>>(adj_row, adj_col, adj_val);

    // layer 1
    gemm_tc<<<gemm_grid, 256>>>(x, W, Wself, b, nullptr, nullptr, nullptr,
                                support, tmp);
    spmm_csr<<<spmm_blocks, 256>>>(support, tmp, statpart);
    reduce_stats<<<1, 256>>>(statpart, stats);

    // layer 2 (BN+ReLU fused into A-load)
    gemm_tc<<<gemm_grid, 256>>>(tmp, W + DD * DD, Wself + DD * DD, b + DD,
                                stats, gamma, beta, support, tmp);
    spmm_csr<<<spmm_blocks, 256>>>(support, tmp, statpart + NCOPY * 2 * DD);
    reduce_stats<<<1, 256>>>(statpart + NCOPY * 2 * DD, stats + 2 * DD);

    node_scores<<<(NN * 32 + 255) / 256, 256>>>(tmp, stats + 2 * DD,
                                                gamma + DD, beta + DD, x, Wc);
    edge_pred<<<(EPRED + 255) / 256, 256>>>(eidx, bc, out);
}